// round 10
// baseline (speedup 1.0000x reference)
#include <cuda_runtime.h>
#include <math.h>

#define NN 10000
#define NE 40000
#define NT 50000
#define NB 64
#define NH 10
#define D1 780
#define D2 7800

#define SL_A1S 0
#define SL_A1D 1
#define SL_B1  2
#define SL_B2  3
#define SL_A2S 4
#define SL_A2D 5
#define SL_BF2 6
#define SL_WO  7

struct GroupPtrs {
    const float* p780[4];
    const float* p7800[2];
    const float* p512[2];
};

// ---------------- scratch ----------------
__device__ unsigned long long g_ptr[8];
__device__ float g_normbuf[8];
__device__ int   g_i64;
__device__ float g_diag[16];
__device__ float g_outtmp[NB];
__device__ float g_h1pre[NN * D1];
__device__ float g_h[NN * D1];
__device__ float g_h2[NN * D1];
__device__ float g_es[NN * NH];
__device__ float g_ed[NN * NH];
__device__ float g_alpha[NT * NH];
__device__ int   g_deg[NN];
__device__ int   g_off[NN + 1];
__device__ int   g_cur[NN];
__device__ int   g_csrc[NT];
__device__ float g_hagg[(size_t)NN * D2];
__device__ float g_W2p[D2 * D1];
__device__ float g_ws2[D1 * NH];
__device__ float g_wd2[D1 * NH];
__device__ float g_gmax[NB * D1];
__device__ float g_gsum[NB * D1];
__device__ int   g_cnt[NB];
__device__ float g_gcat[NB * 1560];
__device__ float g_g1[NB * 1500];
__device__ float g_cat[NB * 256];
__device__ float g_pacc[NB * 26 * 256];
__device__ float g_c[NB * 3872];
__device__ float g_f1[NB * 1024];
__device__ float g_f2[NB * 512];

__device__ __forceinline__ int geti(const int* p, long long i) {
    return g_i64 ? p[2 * i] : p[(size_t)i];
}

__global__ void detect_i64_kernel(const int* __restrict__ ei) {
    int odd_nonzero = 0;
    for (int k = 0; k < 64; k++) if (ei[2 * k + 1] != 0) odd_nonzero++;
    g_i64 = (odd_nonzero == 0) ? 1 : 0;
}

__global__ void norms_kernel(GroupPtrs gp) {
    __shared__ float sred[256];
    int b = blockIdx.x;
    const float* p = nullptr; int n = 0;
    if (b < 4)      { p = gp.p780[b];      n = 780; }
    else if (b < 6) { p = gp.p7800[b - 4]; n = 7800; }
    else            { p = gp.p512[b - 6];  n = 512; }
    float s = 0.f;
    if (p) for (int i = threadIdx.x; i < n; i += 256) s += fabsf(p[i]);
    sred[threadIdx.x] = s;
    __syncthreads();
    for (int d = 128; d > 0; d >>= 1) {
        if (threadIdx.x < d) sred[threadIdx.x] += sred[threadIdx.x + d];
        __syncthreads();
    }
    if (threadIdx.x == 0) g_normbuf[b] = sred[0];
}

__global__ void resolve_kernel(GroupPtrs gp) {
    const float EPS = 1e-12f;
    bool z0 = g_normbuf[6] < EPS, z1 = g_normbuf[7] < EPS;
    if (!z0 && z1) {
        g_ptr[SL_WO]  = (unsigned long long)gp.p512[0];
        g_ptr[SL_BF2] = (unsigned long long)gp.p512[1];
    } else {
        g_ptr[SL_BF2] = (unsigned long long)gp.p512[0];
        g_ptr[SL_WO]  = (unsigned long long)gp.p512[1];
    }
    int za[4], zb[4]; int na = 0, nb = 0;
    for (int i = 0; i < 4; i++) {
        if (g_normbuf[i] < EPS) zb[nb++] = i; else za[na++] = i;
    }
    int ia0 = 0, ia1 = 1, ib0 = 2, ib1 = 3;
    if (na == 2 && nb == 2) { ia0 = za[0]; ia1 = za[1]; ib0 = zb[0]; ib1 = zb[1]; }
    g_ptr[SL_A1S] = (unsigned long long)gp.p780[ia0];
    g_ptr[SL_A1D] = (unsigned long long)gp.p780[ia1];
    g_ptr[SL_B1]  = (unsigned long long)gp.p780[ib0];
    g_ptr[SL_B2]  = (unsigned long long)gp.p780[ib1];
    g_ptr[SL_A2S] = (unsigned long long)gp.p7800[0];
    g_ptr[SL_A2D] = (unsigned long long)gp.p7800[1];
}

// ---------------- prep + CSR ----------------
__global__ void prep_zero_kernel() {
    int i = blockIdx.x * blockDim.x + threadIdx.x;
    if (i < NB * D1) { g_gmax[i] = 0.f; g_gsum[i] = 0.f; }
    if (i < NN) g_deg[i] = 0;
    if (i < NB) g_cnt[i] = 0;
    if (i < 16) g_diag[i] = 0.f;
}

__global__ void count_kernel(const int* __restrict__ ei) {
    int e = blockIdx.x * blockDim.x + threadIdx.x;
    if (e >= NT) return;
    int dst = (e < NE) ? geti(ei, NE + e) : (e - NE);
    if (dst >= 0 && dst < NN) atomicAdd(&g_deg[dst], 1);
}

__global__ void scan_kernel() {
    __shared__ int s[1024];
    int tid = threadIdx.x;
    const int CH = (NN + 1023) / 1024;
    int base = tid * CH;
    int sum = 0;
    for (int i = 0; i < CH; i++) { int idx = base + i; if (idx < NN) sum += g_deg[idx]; }
    s[tid] = sum;
    __syncthreads();
    for (int d = 1; d < 1024; d <<= 1) {
        int v = 0;
        if (tid >= d) v = s[tid - d];
        __syncthreads();
        s[tid] += v;
        __syncthreads();
    }
    int run = (tid == 0) ? 0 : s[tid - 1];
    for (int i = 0; i < CH; i++) {
        int idx = base + i;
        if (idx < NN) { g_off[idx] = run; g_cur[idx] = run; run += g_deg[idx]; }
    }
    if (tid == 1023) g_off[NN] = s[1023];
}

__global__ void scatter_kernel(const int* __restrict__ ei) {
    int e = blockIdx.x * blockDim.x + threadIdx.x;
    if (e >= NT) return;
    int src = (e < NE) ? geti(ei, e) : (e - NE);
    int dst = (e < NE) ? geti(ei, NE + e) : (e - NE);
    if (dst < 0 || dst >= NN || src < 0 || src >= NN) return;
    int pos = atomicAdd(&g_cur[dst], 1);
    if (pos >= 0 && pos < NT) g_csrc[pos] = src;
}

// ---------------- unified simple GEMM ----------------
__global__ __launch_bounds__(128) void gemm8(
    const float* __restrict__ A, const float* B, const float* bias,
    float* __restrict__ C, int M, int K, int N, int act,
    int ldc, int coff, int b_slot, int bias_slot)
{
    __shared__ float sA[8][512];
    if (b_slot >= 0) B = (const float*)g_ptr[b_slot];
    if (bias_slot >= 0) bias = (const float*)g_ptr[bias_slot];
    int n = blockIdx.x * 128 + threadIdx.x;
    int m0 = blockIdx.y * 8;
    float acc[8];
#pragma unroll
    for (int r = 0; r < 8; r++) acc[r] = 0.f;
    for (int k0 = 0; k0 < K; k0 += 512) {
        int kc = min(512, K - k0);
        for (int l = threadIdx.x; l < 8 * kc; l += 128) {
            int r = l / kc, k = l - r * kc;
            int gr = m0 + r;
            sA[r][k] = (gr < M) ? A[(size_t)gr * K + k0 + k] : 0.f;
        }
        __syncthreads();
        if (n < N) {
            for (int k = 0; k < kc; k++) {
                float b = B[(size_t)(k0 + k) * N + n];
#pragma unroll
                for (int r = 0; r < 8; r++) acc[r] += sA[r][k] * b;
            }
        }
        __syncthreads();
    }
    if (n < N) {
        float bv = bias ? bias[n] : 0.f;
#pragma unroll
        for (int r = 0; r < 8; r++) {
            int gr = m0 + r;
            if (gr < M) {
                float v = acc[r] + bv;
                if (act == 1) v = fmaxf(v, 0.f);
                C[(size_t)gr * ldc + coff + n] = v;
            }
        }
    }
}

// ---------------- attention scores ----------------
__global__ void scores1_kernel() {
    const float* a1s = (const float*)g_ptr[SL_A1S];
    const float* a1d = (const float*)g_ptr[SL_A1D];
    int i = blockIdx.x;
    __shared__ float row[D1];
    for (int c = threadIdx.x; c < D1; c += blockDim.x) row[c] = g_h1pre[(size_t)i * D1 + c];
    __syncthreads();
    int t = threadIdx.x;
    if (t < 2 * NH) {
        int hd = t % NH;
        const float* a = (t < NH) ? a1s : a1d;
        float s = 0.f;
        for (int f = 0; f < 78; f++) s += row[hd * 78 + f] * a[hd * 78 + f];
        if (t < NH) g_es[i * NH + hd] = s; else g_ed[i * NH + hd] = s;
    }
}

__global__ void ws2_kernel(const float* __restrict__ W2) {
    const float* a2s = (const float*)g_ptr[SL_A2S];
    const float* a2d = (const float*)g_ptr[SL_A2D];
    int idx = blockIdx.x * blockDim.x + threadIdx.x;
    if (idx >= D1 * NH) return;
    int k = idx / NH, hd = idx % NH;
    float s = 0.f, t = 0.f;
    const float* wrow = &W2[(size_t)k * D2 + hd * D1];
    const float* as = &a2s[hd * D1];
    const float* ad = &a2d[hd * D1];
    for (int f = 0; f < D1; f++) { float w = wrow[f]; s += w * as[f]; t += w * ad[f]; }
    g_ws2[k * NH + hd] = s;
    g_wd2[k * NH + hd] = t;
}

__global__ void scores2_kernel() {
    int i = blockIdx.x;
    __shared__ float row[D1];
    for (int c = threadIdx.x; c < D1; c += blockDim.x) row[c] = g_h[(size_t)i * D1 + c];
    __syncthreads();
    int t = threadIdx.x;
    if (t < 2 * NH) {
        int hd = t % NH;
        const float* w = (t < NH) ? g_ws2 : g_wd2;
        float s = 0.f;
        for (int k = 0; k < D1; k++) s += row[k] * w[k * NH + hd];
        if (t < NH) g_es[i * NH + hd] = s; else g_ed[i * NH + hd] = s;
    }
}

__global__ void alpha_kernel() {
    int idx = blockIdx.x * blockDim.x + threadIdx.x;
    if (idx >= NN * NH) return;
    int d = idx / NH, hd = idx - d * NH;
    int s = g_off[d], e = g_off[d + 1];
    if (e <= s) return;
    float edv = g_ed[idx];
    float m = -1e30f;
    for (int j = s; j < e; j++) {
        float z = g_es[g_csrc[j] * NH + hd] + edv;
        z = (z > 0.f) ? z : 0.2f * z;
        m = fmaxf(m, z);
    }
    float sum = 0.f;
    for (int j = s; j < e; j++) {
        float z = g_es[g_csrc[j] * NH + hd] + edv;
        z = (z > 0.f) ? z : 0.2f * z;
        float ex = expf(z - m);
        g_alpha[j * NH + hd] = ex;
        sum += ex;
    }
    float inv = 1.f / sum;
    for (int j = s; j < e; j++) g_alpha[j * NH + hd] *= inv;
}

__global__ __launch_bounds__(256) void agg1_kernel() {
    const float* b1 = (const float*)g_ptr[SL_B1];
    int d = blockIdx.x;
    int s = g_off[d], e = g_off[d + 1];
    __shared__ int ssrc[64];
    __shared__ float sal[64 * NH];
    float acc[4] = {0.f, 0.f, 0.f, 0.f};
    int hd[4];
#pragma unroll
    for (int u = 0; u < 4; u++) {
        int c = threadIdx.x + u * 256;
        hd[u] = (c < D1) ? (c / 78) : 0;
    }
    for (int j0 = s; j0 < e; j0 += 64) {
        int cnt = min(64, e - j0);
        for (int q = threadIdx.x; q < cnt; q += 256) ssrc[q] = g_csrc[j0 + q];
        for (int q = threadIdx.x; q < cnt * NH; q += 256) sal[q] = g_alpha[j0 * NH + q];
        __syncthreads();
        for (int jj = 0; jj < cnt; jj++) {
            const float* hr = &g_h1pre[(size_t)ssrc[jj] * D1];
#pragma unroll
            for (int u = 0; u < 4; u++) {
                int c = threadIdx.x + u * 256;
                if (c < D1) acc[u] += sal[jj * NH + hd[u]] * hr[c];
            }
        }
        __syncthreads();
    }
#pragma unroll
    for (int u = 0; u < 4; u++) {
        int c = threadIdx.x + u * 256;
        if (c < D1) {
            float z = acc[u] + b1[c];
            g_h[(size_t)d * D1 + c] = (z > 0.f) ? z : (expf(z) - 1.f);
        }
    }
}

__global__ __launch_bounds__(256) void agg2_kernel() {
    int d = blockIdx.x;
    int s = g_off[d], e = g_off[d + 1];
    __shared__ int ssrc[32];
    __shared__ float sal[32 * NH];
    float acc[4][NH];
#pragma unroll
    for (int u = 0; u < 4; u++)
#pragma unroll
        for (int t = 0; t < NH; t++) acc[u][t] = 0.f;
    for (int j0 = s; j0 < e; j0 += 32) {
        int cnt = min(32, e - j0);
        for (int q = threadIdx.x; q < cnt; q += 256) ssrc[q] = g_csrc[j0 + q];
        for (int q = threadIdx.x; q < cnt * NH; q += 256) sal[q] = g_alpha[j0 * NH + q];
        __syncthreads();
        for (int jj = 0; jj < cnt; jj++) {
            const float* hr = &g_h[(size_t)ssrc[jj] * D1];
#pragma unroll
            for (int u = 0; u < 4; u++) {
                int c = threadIdx.x + u * 256;
                if (c < D1) {
                    float v = hr[c];
#pragma unroll
                    for (int t = 0; t < NH; t++) acc[u][t] += sal[jj * NH + t] * v;
                }
            }
        }
        __syncthreads();
    }
#pragma unroll
    for (int u = 0; u < 4; u++) {
        int c = threadIdx.x + u * 256;
        if (c < D1) {
#pragma unroll
            for (int t = 0; t < NH; t++)
                g_hagg[(size_t)d * D2 + t * D1 + c] = acc[u][t];
        }
    }
}

__global__ void packw2_kernel(const float* __restrict__ W2) {
    int idx = blockIdx.x * blockDim.x + threadIdx.x;
    if (idx >= D2 * D1) return;
    int f = idx % D1;
    int kk = idx / D1;
    int hd = kk / D1;
    int k = kk - hd * D1;
    g_W2p[idx] = 0.1f * W2[(size_t)k * D2 + hd * D1 + f];
}

// ---------------- pooling ----------------
__global__ void cnt_kernel(const int* __restrict__ batch) {
    int n = blockIdx.x * blockDim.x + threadIdx.x;
    if (n < NN) {
        int b = geti(batch, n);
        if (b >= 0 && b < NB) atomicAdd(&g_cnt[b], 1);
    }
}

__global__ void pool_kernel(const int* __restrict__ batch) {
    int idx = blockIdx.x * blockDim.x + threadIdx.x;
    if (idx >= NN * D1) return;
    int n = idx / D1, c = idx - n * D1;
    int b = geti(batch, n);
    if (b < 0 || b >= NB) return;
    float v = g_h2[idx];
    atomicAdd(&g_gsum[b * D1 + c], v);
    atomicMax((int*)&g_gmax[b * D1 + c], __float_as_int(v));
}

__global__ void gcat_kernel() {
    int idx = blockIdx.x * blockDim.x + threadIdx.x;
    if (idx >= NB * 1560) return;
    int b = idx / 1560, c = idx - b * 1560;
    float v;
    if (c < D1) v = g_gmax[b * D1 + c];
    else v = g_gsum[b * D1 + c - D1] / fmaxf((float)g_cnt[b], 1.f);
    g_gcat[idx] = v;
}

// ---------------- protein branch ----------------
__global__ void paccum_kernel(const int* __restrict__ target, const float* __restrict__ Wc) {
    int b = blockIdx.x;
    int tid = threadIdx.x;
    __shared__ int tg[1000];
    for (int i = tid; i < 1000; i += 256) {
        int v = geti(target, (long long)b * 1000 + i);
        tg[i] = (v >= 0 && v < 26) ? v : 0;
    }
    __syncthreads();
    float acc[26];
#pragma unroll
    for (int v = 0; v < 26; v++) acc[v] = 0.f;
    int o = tid >> 3, k = tid & 7;
    for (int i = 0; i < 1000; i++) acc[tg[i]] += Wc[o * 8000 + i * 8 + k];
#pragma unroll
    for (int v = 0; v < 26; v++) g_pacc[(b * 26 + v) * 256 + tid] = acc[v];
}

__global__ void conv_kernel(const float* __restrict__ emb, const float* __restrict__ bc) {
    int o = blockIdx.x, b = blockIdx.y;
    __shared__ float sA[26 * 8];
    for (int i = threadIdx.x; i < 208; i += 128)
        sA[i] = g_pacc[(b * 26 + (i >> 3)) * 256 + o * 8 + (i & 7)];
    __syncthreads();
    int t = threadIdx.x;
    if (t < 121) {
        float s = 0.f;
#pragma unroll
        for (int v = 0; v < 26; v++)
#pragma unroll
            for (int k = 0; k < 8; k++) s += sA[v * 8 + k] * emb[v * 128 + t + k];
        g_c[b * 3872 + o * 121 + t] = s + bc[o];
    }
}

// ---------------- diagnostics ----------------
__global__ void check_kernel(const float* __restrict__ xp, const float* __restrict__ w1p) {
    __shared__ float sred[256];
    int q = blockIdx.x;
    int tid = blockIdx.y * 256 + threadIdx.x;
    int stride = gridDim.y * 256;
    float s = 0.f;
    if (q == 0) {
        for (int i = tid; i < 780000; i += stride) s += fabsf(xp[i]);
    } else if (q == 1) {
        for (int i = tid; i < 60840; i += stride) s += fabsf(w1p[i]);
    } else if (q == 2) {
        for (size_t i = tid; i < (size_t)NN * D1; i += stride) s += fabsf(g_h1pre[i]);
    } else if (q == 3) {
        for (size_t i = tid; i < (size_t)NN * D1; i += stride) s += fabsf(g_h[i]);
    } else if (q == 4) {
        for (size_t i = tid; i < (size_t)NN * D1; i += stride) s += fabsf(g_h2[i]);
    } else if (q == 5) {
        for (int i = tid; i < NB * 1560; i += stride) s += fabsf(g_gcat[i]);
    } else if (q == 6) {
        for (int i = tid; i < NB * 128; i += stride)
            s += fabsf(g_cat[(i >> 7) * 256 + (i & 127)]);
    } else if (q == 7) {
        for (int i = tid; i < NB * 128; i += stride)
            s += fabsf(g_cat[(i >> 7) * 256 + 128 + (i & 127)]);
    } else if (q == 8) {
        for (int i = tid; i < NB * 512; i += stride) s += fabsf(g_f2[i]);
    } else {
        const float* wo = (const float*)g_ptr[SL_WO];
        for (int i = tid; i < 512; i += stride) s += fabsf(wo[i]);
    }
    sred[threadIdx.x] = s;
    __syncthreads();
    for (int d = 128; d > 0; d >>= 1) {
        if (threadIdx.x < d) sred[threadIdx.x] += sred[threadIdx.x + d];
        __syncthreads();
    }
    if (threadIdx.x == 0) atomicAdd(&g_diag[q], sred[0]);
}

__global__ void writer_kernel(float* __restrict__ out) {
    __shared__ float code_s;
    int m = threadIdx.x;
    if (m == 0) {
        const float EPS = 1e-6f;
        float code = 0.f;
        bool bad = false; float so = 0.f;
        for (int i = 0; i < NB; i++) {
            float v = g_outtmp[i];
            if (!(v == v) || fabsf(v) > 1e30f) bad = true;
            so += fabsf(v);
        }
        if      (g_diag[0] < EPS) code = 100.f;
        else if (g_diag[1] < EPS) code = 200.f;
        else if (g_diag[2] < EPS) code = 400.f;
        else if (g_off[NN] != NT) code = 800.f;
        else if (g_diag[3] < EPS) code = 1600.f;
        else if (g_diag[4] < EPS) code = 3200.f;
        else if (g_diag[5] < EPS) code = 6400.f;
        else if (g_diag[6] < EPS) code = 12800.f;
        else if (g_diag[7] < EPS) code = 25600.f;
        else if (g_diag[8] < EPS) code = 51200.f;
        else if (g_diag[9] < EPS) code = 102400.f;
        if (bad) code = 204800.f;
        else if (code == 0.f && so < 1e-12f) code = 409600.f;
        code_s = code;
    }
    __syncthreads();
    out[m] = (code_s == 0.f) ? g_outtmp[m] : code_s;
}

// ---------------- launcher ----------------
static int find_sz(const int* in_sizes, int n_in, long long want,
                   unsigned char* used, int fallback) {
    for (int i = 0; i < n_in; i++)
        if (!used[i] && (long long)in_sizes[i] == want) { used[i] = 1; return i; }
    if (fallback >= 0 && fallback < n_in) return fallback;
    return 0;
}

template <typename T>
static T* sym_addr(const void* symbol) {
    void* p = nullptr;
    cudaGetSymbolAddress(&p, symbol);
    return (T*)p;
}

extern "C" void kernel_launch(void* const* d_in, const int* in_sizes, int n_in,
                              void* d_out, int out_size) {
    long long S = 0;
    for (int i = 0; i < n_in; i++) if (in_sizes[i] == 780000)  { S = 1; break; }
    if (!S) { for (int i = 0; i < n_in; i++) if (in_sizes[i] == 3120000) { S = 4; break; } }
    if (!S) S = 1;

    // REAL device addresses of scratch buffers (the round-1..8 bug: passing the
    // __device__ symbol from host code passes the HOST shadow address, and on
    // GB300's ATS the device happily writes into host RAM — silently).
    float* p_h1pre = sym_addr<float>(g_h1pre);
    float* p_h2    = sym_addr<float>(g_h2);
    float* p_hagg  = sym_addr<float>(g_hagg);
    float* p_W2p   = sym_addr<float>(g_W2p);
    float* p_gcat  = sym_addr<float>(g_gcat);
    float* p_g1    = sym_addr<float>(g_g1);
    float* p_cat   = sym_addr<float>(g_cat);
    float* p_c     = sym_addr<float>(g_c);
    float* p_f1    = sym_addr<float>(g_f1);
    float* p_f2    = sym_addr<float>(g_f2);
    float* p_outt  = sym_addr<float>(g_outtmp);

    GroupPtrs gp;
    const float* g128p[2] = {nullptr, nullptr};
    int n780 = 0, n7800 = 0, n512 = 0, n128 = 0;
    for (int i = 0; i < 4; i++) gp.p780[i] = nullptr;
    gp.p7800[0] = gp.p7800[1] = nullptr;
    gp.p512[0] = gp.p512[1] = nullptr;
    for (int i = 0; i < n_in; i++) {
        long long sz = in_sizes[i];
        if (sz == 780 * S  && n780  < 4) gp.p780[n780++]   = (const float*)d_in[i];
        else if (sz == 7800 * S && n7800 < 2) gp.p7800[n7800++] = (const float*)d_in[i];
        else if (sz == 512 * S  && n512  < 2) gp.p512[n512++]   = (const float*)d_in[i];
        else if (sz == 128 * S  && n128  < 2) g128p[n128++]     = (const float*)d_in[i];
    }
    for (int i = 0; i < 4; i++) if (!gp.p780[i])  gp.p780[i]  = (const float*)d_in[0];
    for (int i = 0; i < 2; i++) if (!gp.p7800[i]) gp.p7800[i] = (const float*)d_in[0];
    for (int i = 0; i < 2; i++) if (!gp.p512[i])  gp.p512[i]  = (const float*)d_in[0];
    for (int i = 0; i < 2; i++) if (!g128p[i])    g128p[i]    = (const float*)d_in[0];

    unsigned char used[256];
    for (int i = 0; i < 256; i++) used[i] = 0;
    const float* x      = (const float*)d_in[find_sz(in_sizes, n_in, 780000 * S, used, 0)];
    const int*   ei     = (const int*)  d_in[find_sz(in_sizes, n_in, 80000 * S,  used, 1)];
    const int*   batch  = (const int*)  d_in[find_sz(in_sizes, n_in, 10000 * S,  used, 2)];
    const int*   target = (const int*)  d_in[find_sz(in_sizes, n_in, 64000 * S,  used, 3)];
    const float* W1     = (const float*)d_in[find_sz(in_sizes, n_in, 60840 * S,  used, 4)];
    const float* W2     = (const float*)d_in[find_sz(in_sizes, n_in, 6084000 * S, used, 8)];
    const float* Wg1    = (const float*)d_in[find_sz(in_sizes, n_in, 2340000 * S, used, 12)];
    const float* bg1    = (const float*)d_in[find_sz(in_sizes, n_in, 1500 * S,   used, 13)];
    const float* Wg2    = (const float*)d_in[find_sz(in_sizes, n_in, 192000 * S, used, 14)];
    const float* emb    = (const float*)d_in[find_sz(in_sizes, n_in, 3328 * S,   used, 16)];
    const float* Wc     = (const float*)d_in[find_sz(in_sizes, n_in, 256000 * S, used, 17)];
    const float* bc     = (const float*)d_in[find_sz(in_sizes, n_in, 32 * S,     used, 18)];
    const float* Wxt    = (const float*)d_in[find_sz(in_sizes, n_in, 495616 * S, used, 19)];
    const float* Wf1    = (const float*)d_in[find_sz(in_sizes, n_in, 262144 * S, used, 21)];
    const float* bf1    = (const float*)d_in[find_sz(in_sizes, n_in, 1024 * S,   used, 22)];
    const float* Wf2    = (const float*)d_in[find_sz(in_sizes, n_in, 524288 * S, used, 23)];
    const float* bo     = (const float*)d_in[find_sz(in_sizes, n_in, 1 * S,      used, 26)];
    const float* bg2 = g128p[0];
    const float* bxt = g128p[1];
    float* out = (float*)d_out;

    detect_i64_kernel<<<1, 1>>>(ei);
    norms_kernel<<<8, 256>>>(gp);
    resolve_kernel<<<1, 1>>>(gp);

    prep_zero_kernel<<<(NB * D1 + 255) / 256, 256>>>();
    count_kernel<<<(NT + 255) / 256, 256>>>(ei);
    scan_kernel<<<1, 1024>>>();
    scatter_kernel<<<(NT + 255) / 256, 256>>>(ei);

    // GAT1
    gemm8<<<dim3(7, (NN + 7) / 8), 128>>>(x, W1, nullptr, p_h1pre, NN, 78, D1, 0, D1, 0, -1, -1);
    scores1_kernel<<<NN, 128>>>();
    alpha_kernel<<<(NN * NH + 255) / 256, 256>>>();
    agg1_kernel<<<NN, 256>>>();

    // GAT2
    ws2_kernel<<<(D1 * NH + 255) / 256, 256>>>(W2);
    scores2_kernel<<<NN, 128>>>();
    alpha_kernel<<<(NN * NH + 255) / 256, 256>>>();
    agg2_kernel<<<NN, 256>>>();
    packw2_kernel<<<(D2 * D1 + 255) / 256, 256>>>(W2);
    gemm8<<<dim3(7, (NN + 7) / 8), 128>>>(p_hagg, p_W2p, nullptr, p_h2, NN, D2, D1, 1, D1, 0, -1, SL_B2);

    // pooling + graph MLP
    cnt_kernel<<<(NN + 255) / 256, 256>>>(batch);
    pool_kernel<<<(NN * D1 + 255) / 256, 256>>>(batch);
    gcat_kernel<<<(NB * 1560 + 255) / 256, 256>>>();
    gemm8<<<dim3(12, 8), 128>>>(p_gcat, Wg1, bg1, p_g1, NB, 1560, 1500, 1, 1500, 0, -1, -1);
    gemm8<<<dim3(1, 8), 128>>>(p_g1, Wg2, bg2, p_cat, NB, 1500, 128, 1, 256, 0, -1, -1);

    // protein branch
    paccum_kernel<<<NB, 256>>>(target, Wc);
    conv_kernel<<<dim3(32, NB), 128>>>(emb, bc);
    gemm8<<<dim3(1, 8), 128>>>(p_c, Wxt, bxt, p_cat, NB, 3872, 128, 0, 256, 128, -1, -1);

    // head MLP
    gemm8<<<dim3(8, 8), 128>>>(p_cat, Wf1, bf1, p_f1, NB, 256, 1024, 1, 1024, 0, -1, -1);
    gemm8<<<dim3(4, 8), 128>>>(p_f1, Wf2, nullptr, p_f2, NB, 1024, 512, 1, 512, 0, -1, SL_BF2);
    gemm8<<<dim3(1, 8), 128>>>(p_f2, nullptr, bo, p_outt, NB, 512, 1, 0, 1, 0, SL_WO, -1);

    // diagnostics + final write
    check_kernel<<<dim3(10, 32), 256>>>(x, W1);
    writer_kernel<<<1, NB>>>(out);
}

// round 13
// speedup vs baseline: 1.2995x; 1.2995x over previous
#include <cuda_runtime.h>
#include <math.h>

#define NN 10000
#define NE 40000
#define NT 50000
#define NB 64
#define NH 10
#define D1 780
#define D2 7800

#define SL_A1S 0
#define SL_A1D 1
#define SL_B1  2
#define SL_B2  3
#define SL_A2S 4
#define SL_A2D 5
#define SL_BF2 6
#define SL_WO  7

struct GroupPtrs {
    const float* p780[4];
    const float* p7800[2];
    const float* p512[2];
};

// ---------------- scratch ----------------
__device__ unsigned long long g_ptr[8];
__device__ float g_normbuf[8];
__device__ int   g_i64;
__device__ float g_h1pre[NN * D1];
__device__ float g_h[NN * D1];
__device__ float g_h2[NN * D1];
__device__ float g_es[NN * NH];
__device__ float g_ed[NN * NH];
__device__ float g_alpha[NT * NH];
__device__ int   g_deg[NN];
__device__ int   g_off[NN + 1];
__device__ int   g_cur[NN];
__device__ int   g_csrc[NT];
__device__ float g_hagg[(size_t)NN * D2];
__device__ float g_W2p[D2 * D1];
__device__ float g_ws2[D1 * NH];
__device__ float g_wd2[D1 * NH];
__device__ int   g_bnd[NB + 1];
__device__ float g_gcat[NB * 1560];
__device__ float g_g1[NB * 1500];
__device__ float g_cat[NB * 256];
__device__ float g_pacc[NB * 26 * 256];
__device__ float g_c[NB * 3872];
__device__ float g_f1[NB * 1024];
__device__ float g_f2[NB * 512];

__device__ __forceinline__ int geti(const int* p, long long i) {
    return g_i64 ? p[2 * i] : p[(size_t)i];
}

__global__ void detect_i64_kernel(const int* __restrict__ ei) {
    int odd_nonzero = 0;
    for (int k = 0; k < 64; k++) if (ei[2 * k + 1] != 0) odd_nonzero++;
    g_i64 = (odd_nonzero == 0) ? 1 : 0;
}

__global__ void norms_kernel(GroupPtrs gp) {
    __shared__ float sred[256];
    int b = blockIdx.x;
    const float* p = nullptr; int n = 0;
    if (b < 4)      { p = gp.p780[b];      n = 780; }
    else if (b < 6) { p = gp.p7800[b - 4]; n = 7800; }
    else            { p = gp.p512[b - 6];  n = 512; }
    float s = 0.f;
    if (p) for (int i = threadIdx.x; i < n; i += 256) s += fabsf(p[i]);
    sred[threadIdx.x] = s;
    __syncthreads();
    for (int d = 128; d > 0; d >>= 1) {
        if (threadIdx.x < d) sred[threadIdx.x] += sred[threadIdx.x + d];
        __syncthreads();
    }
    if (threadIdx.x == 0) g_normbuf[b] = sred[0];
}

__global__ void resolve_kernel(GroupPtrs gp) {
    const float EPS = 1e-12f;
    bool z0 = g_normbuf[6] < EPS, z1 = g_normbuf[7] < EPS;
    if (!z0 && z1) {
        g_ptr[SL_WO]  = (unsigned long long)gp.p512[0];
        g_ptr[SL_BF2] = (unsigned long long)gp.p512[1];
    } else {
        g_ptr[SL_BF2] = (unsigned long long)gp.p512[0];
        g_ptr[SL_WO]  = (unsigned long long)gp.p512[1];
    }
    int za[4], zb[4]; int na = 0, nb = 0;
    for (int i = 0; i < 4; i++) {
        if (g_normbuf[i] < EPS) zb[nb++] = i; else za[na++] = i;
    }
    int ia0 = 0, ia1 = 1, ib0 = 2, ib1 = 3;
    if (na == 2 && nb == 2) { ia0 = za[0]; ia1 = za[1]; ib0 = zb[0]; ib1 = zb[1]; }
    g_ptr[SL_A1S] = (unsigned long long)gp.p780[ia0];
    g_ptr[SL_A1D] = (unsigned long long)gp.p780[ia1];
    g_ptr[SL_B1]  = (unsigned long long)gp.p780[ib0];
    g_ptr[SL_B2]  = (unsigned long long)gp.p780[ib1];
    g_ptr[SL_A2S] = (unsigned long long)gp.p7800[0];
    g_ptr[SL_A2D] = (unsigned long long)gp.p7800[1];
}

// ---------------- prep + CSR ----------------
__global__ void prep_zero_kernel() {
    int i = blockIdx.x * blockDim.x + threadIdx.x;
    if (i < NN) g_deg[i] = 0;
}

__global__ void count_kernel(const int* __restrict__ ei) {
    int e = blockIdx.x * blockDim.x + threadIdx.x;
    if (e >= NT) return;
    int dst = (e < NE) ? geti(ei, NE + e) : (e - NE);
    if (dst >= 0 && dst < NN) atomicAdd(&g_deg[dst], 1);
}

__global__ void scan_kernel() {
    __shared__ int s[1024];
    int tid = threadIdx.x;
    const int CH = (NN + 1023) / 1024;
    int base = tid * CH;
    int sum = 0;
    for (int i = 0; i < CH; i++) { int idx = base + i; if (idx < NN) sum += g_deg[idx]; }
    s[tid] = sum;
    __syncthreads();
    for (int d = 1; d < 1024; d <<= 1) {
        int v = 0;
        if (tid >= d) v = s[tid - d];
        __syncthreads();
        s[tid] += v;
        __syncthreads();
    }
    int run = (tid == 0) ? 0 : s[tid - 1];
    for (int i = 0; i < CH; i++) {
        int idx = base + i;
        if (idx < NN) { g_off[idx] = run; g_cur[idx] = run; run += g_deg[idx]; }
    }
    if (tid == 1023) g_off[NN] = s[1023];
}

__global__ void scatter_kernel(const int* __restrict__ ei) {
    int e = blockIdx.x * blockDim.x + threadIdx.x;
    if (e >= NT) return;
    int src = (e < NE) ? geti(ei, e) : (e - NE);
    int dst = (e < NE) ? geti(ei, NE + e) : (e - NE);
    if (dst < 0 || dst >= NN || src < 0 || src >= NN) return;
    int pos = atomicAdd(&g_cur[dst], 1);
    if (pos >= 0 && pos < NT) g_csrc[pos] = src;
}

// ---------------- tiled SGEMM with packed f32x2 FMA ----------------
// C[M,N] = act( A[M,K] @ B[K,N] + bias )
// 128x128 tile, 8x8 microtile per thread, 256 threads.
__global__ __launch_bounds__(256) void sgemm128(
    const float* __restrict__ A, const float* __restrict__ B,
    const float* bias, float* __restrict__ C,
    int M, int K, int N, int act, int bias_slot)
{
    __shared__ float As[8][128];
    __shared__ float Bs[8][128];
    if (bias_slot >= 0) bias = (const float*)g_ptr[bias_slot];
    int tid = threadIdx.x;
    int tx = tid & 15, ty = tid >> 4;
    int rowBase = blockIdx.y * 128, colBase = blockIdx.x * 128;
    unsigned long long acc2[8][4];
#pragma unroll
    for (int i = 0; i < 8; i++)
#pragma unroll
        for (int j = 0; j < 4; j++) acc2[i][j] = 0ULL;

    for (int k0 = 0; k0 < K; k0 += 8) {
#pragma unroll
        for (int i = 0; i < 4; i++) {
            int l = i * 256 + tid;
            int r = l >> 3, k = l & 7;
            int gr = rowBase + r, gk = k0 + k;
            As[k][r] = (gr < M && gk < K) ? A[(size_t)gr * K + gk] : 0.f;
        }
#pragma unroll
        for (int i = 0; i < 4; i++) {
            int l = i * 256 + tid;
            int k = l >> 7, c = l & 127;
            int gk = k0 + k, gc = colBase + c;
            Bs[k][c] = (gk < K && gc < N) ? B[(size_t)gk * N + gc] : 0.f;
        }
        __syncthreads();
#pragma unroll
        for (int k = 0; k < 8; k++) {
            float4 a0 = *reinterpret_cast<const float4*>(&As[k][ty * 8]);
            float4 a1 = *reinterpret_cast<const float4*>(&As[k][ty * 8 + 4]);
            float a[8] = {a0.x, a0.y, a0.z, a0.w, a1.x, a1.y, a1.z, a1.w};
            const float2* bp = reinterpret_cast<const float2*>(&Bs[k][tx * 8]);
            unsigned long long b2[4];
#pragma unroll
            for (int j = 0; j < 4; j++) {
                float2 bv = bp[j];
                asm("mov.b64 %0, {%1, %2};" : "=l"(b2[j]) : "f"(bv.x), "f"(bv.y));
            }
#pragma unroll
            for (int i = 0; i < 8; i++) {
                unsigned long long a2;
                asm("mov.b64 %0, {%1, %1};" : "=l"(a2) : "f"(a[i]));
#pragma unroll
                for (int j = 0; j < 4; j++)
                    asm("fma.rn.f32x2 %0, %1, %2, %0;"
                        : "+l"(acc2[i][j]) : "l"(a2), "l"(b2[j]));
            }
        }
        __syncthreads();
    }
#pragma unroll
    for (int i = 0; i < 8; i++) {
        int r = rowBase + ty * 8 + i;
        if (r < M) {
#pragma unroll
            for (int j = 0; j < 4; j++) {
                float lo, hi;
                asm("mov.b64 {%0, %1}, %2;" : "=f"(lo), "=f"(hi) : "l"(acc2[i][j]));
                int c0 = colBase + tx * 8 + 2 * j;
                if (c0 < N) {
                    float v = lo + (bias ? bias[c0] : 0.f);
                    if (act == 1) v = fmaxf(v, 0.f);
                    C[(size_t)r * N + c0] = v;
                }
                if (c0 + 1 < N) {
                    float v = hi + (bias ? bias[c0 + 1] : 0.f);
                    if (act == 1) v = fmaxf(v, 0.f);
                    C[(size_t)r * N + c0 + 1] = v;
                }
            }
        }
    }
}

// ---------------- small GEMM (kept for tail layers) ----------------
__global__ __launch_bounds__(128) void gemm8(
    const float* __restrict__ A, const float* B, const float* bias,
    float* __restrict__ C, int M, int K, int N, int act,
    int ldc, int coff, int b_slot, int bias_slot)
{
    __shared__ float sA[8][512];
    if (b_slot >= 0) B = (const float*)g_ptr[b_slot];
    if (bias_slot >= 0) bias = (const float*)g_ptr[bias_slot];
    int n = blockIdx.x * 128 + threadIdx.x;
    int m0 = blockIdx.y * 8;
    float acc[8];
#pragma unroll
    for (int r = 0; r < 8; r++) acc[r] = 0.f;
    for (int k0 = 0; k0 < K; k0 += 512) {
        int kc = min(512, K - k0);
        for (int l = threadIdx.x; l < 8 * kc; l += 128) {
            int r = l / kc, k = l - r * kc;
            int gr = m0 + r;
            sA[r][k] = (gr < M) ? A[(size_t)gr * K + k0 + k] : 0.f;
        }
        __syncthreads();
        if (n < N) {
            for (int k = 0; k < kc; k++) {
                float b = B[(size_t)(k0 + k) * N + n];
#pragma unroll
                for (int r = 0; r < 8; r++) acc[r] += sA[r][k] * b;
            }
        }
        __syncthreads();
    }
    if (n < N) {
        float bv = bias ? bias[n] : 0.f;
#pragma unroll
        for (int r = 0; r < 8; r++) {
            int gr = m0 + r;
            if (gr < M) {
                float v = acc[r] + bv;
                if (act == 1) v = fmaxf(v, 0.f);
                C[(size_t)gr * ldc + coff + n] = v;
            }
        }
    }
}

// ---------------- attention scores ----------------
__global__ void scores1_kernel() {
    const float* a1s = (const float*)g_ptr[SL_A1S];
    const float* a1d = (const float*)g_ptr[SL_A1D];
    int i = blockIdx.x;
    __shared__ float row[D1];
    for (int c = threadIdx.x; c < D1; c += blockDim.x) row[c] = g_h1pre[(size_t)i * D1 + c];
    __syncthreads();
    int t = threadIdx.x;
    if (t < 2 * NH) {
        int hd = t % NH;
        const float* a = (t < NH) ? a1s : a1d;
        float s = 0.f;
        for (int f = 0; f < 78; f++) s += row[hd * 78 + f] * a[hd * 78 + f];
        if (t < NH) g_es[i * NH + hd] = s; else g_ed[i * NH + hd] = s;
    }
}

__global__ void ws2_kernel(const float* __restrict__ W2) {
    const float* a2s = (const float*)g_ptr[SL_A2S];
    const float* a2d = (const float*)g_ptr[SL_A2D];
    int idx = blockIdx.x * blockDim.x + threadIdx.x;
    if (idx >= D1 * NH) return;
    int k = idx / NH, hd = idx % NH;
    float s = 0.f, t = 0.f;
    const float* wrow = &W2[(size_t)k * D2 + hd * D1];
    const float* as = &a2s[hd * D1];
    const float* ad = &a2d[hd * D1];
    for (int f = 0; f < D1; f++) { float w = wrow[f]; s += w * as[f]; t += w * ad[f]; }
    g_ws2[k * NH + hd] = s;
    g_wd2[k * NH + hd] = t;
}

__global__ void scores2_kernel() {
    int i = blockIdx.x;
    __shared__ float row[D1];
    for (int c = threadIdx.x; c < D1; c += blockDim.x) row[c] = g_h[(size_t)i * D1 + c];
    __syncthreads();
    int t = threadIdx.x;
    if (t < 2 * NH) {
        int hd = t % NH;
        const float* w = (t < NH) ? g_ws2 : g_wd2;
        float s = 0.f;
        for (int k = 0; k < D1; k++) s += row[k] * w[k * NH + hd];
        if (t < NH) g_es[i * NH + hd] = s; else g_ed[i * NH + hd] = s;
    }
}

__global__ void alpha_kernel() {
    int idx = blockIdx.x * blockDim.x + threadIdx.x;
    if (idx >= NN * NH) return;
    int d = idx / NH, hd = idx - d * NH;
    int s = g_off[d], e = g_off[d + 1];
    if (e <= s) return;
    float edv = g_ed[idx];
    float m = -1e30f;
    for (int j = s; j < e; j++) {
        float z = g_es[g_csrc[j] * NH + hd] + edv;
        z = (z > 0.f) ? z : 0.2f * z;
        m = fmaxf(m, z);
    }
    float sum = 0.f;
    for (int j = s; j < e; j++) {
        float z = g_es[g_csrc[j] * NH + hd] + edv;
        z = (z > 0.f) ? z : 0.2f * z;
        float ex = expf(z - m);
        g_alpha[j * NH + hd] = ex;
        sum += ex;
    }
    float inv = 1.f / sum;
    for (int j = s; j < e; j++) g_alpha[j * NH + hd] *= inv;
}

__global__ __launch_bounds__(256) void agg1_kernel() {
    const float* b1 = (const float*)g_ptr[SL_B1];
    int d = blockIdx.x;
    int s = g_off[d], e = g_off[d + 1];
    __shared__ int ssrc[64];
    __shared__ float sal[64 * NH];
    float acc[4] = {0.f, 0.f, 0.f, 0.f};
    int hd[4];
#pragma unroll
    for (int u = 0; u < 4; u++) {
        int c = threadIdx.x + u * 256;
        hd[u] = (c < D1) ? (c / 78) : 0;
    }
    for (int j0 = s; j0 < e; j0 += 64) {
        int cnt = min(64, e - j0);
        for (int q = threadIdx.x; q < cnt; q += 256) ssrc[q] = g_csrc[j0 + q];
        for (int q = threadIdx.x; q < cnt * NH; q += 256) sal[q] = g_alpha[j0 * NH + q];
        __syncthreads();
        for (int jj = 0; jj < cnt; jj++) {
            const float* hr = &g_h1pre[(size_t)ssrc[jj] * D1];
#pragma unroll
            for (int u = 0; u < 4; u++) {
                int c = threadIdx.x + u * 256;
                if (c < D1) acc[u] += sal[jj * NH + hd[u]] * hr[c];
            }
        }
        __syncthreads();
    }
#pragma unroll
    for (int u = 0; u < 4; u++) {
        int c = threadIdx.x + u * 256;
        if (c < D1) {
            float z = acc[u] + b1[c];
            g_h[(size_t)d * D1 + c] = (z > 0.f) ? z : (expf(z) - 1.f);
        }
    }
}

__global__ __launch_bounds__(256) void agg2_kernel() {
    int d = blockIdx.x;
    int s = g_off[d], e = g_off[d + 1];
    __shared__ int ssrc[32];
    __shared__ float sal[32 * NH];
    float acc[4][NH];
#pragma unroll
    for (int u = 0; u < 4; u++)
#pragma unroll
        for (int t = 0; t < NH; t++) acc[u][t] = 0.f;
    for (int j0 = s; j0 < e; j0 += 32) {
        int cnt = min(32, e - j0);
        for (int q = threadIdx.x; q < cnt; q += 256) ssrc[q] = g_csrc[j0 + q];
        for (int q = threadIdx.x; q < cnt * NH; q += 256) sal[q] = g_alpha[j0 * NH + q];
        __syncthreads();
        for (int jj = 0; jj < cnt; jj++) {
            const float* hr = &g_h[(size_t)ssrc[jj] * D1];
#pragma unroll
            for (int u = 0; u < 4; u++) {
                int c = threadIdx.x + u * 256;
                if (c < D1) {
                    float v = hr[c];
#pragma unroll
                    for (int t = 0; t < NH; t++) acc[u][t] += sal[jj * NH + t] * v;
                }
            }
        }
        __syncthreads();
    }
#pragma unroll
    for (int u = 0; u < 4; u++) {
        int c = threadIdx.x + u * 256;
        if (c < D1) {
#pragma unroll
            for (int t = 0; t < NH; t++)
                g_hagg[(size_t)d * D2 + t * D1 + c] = acc[u][t];
        }
    }
}

__global__ void packw2_kernel(const float* __restrict__ W2) {
    int idx = blockIdx.x * blockDim.x + threadIdx.x;
    if (idx >= D2 * D1) return;
    int f = idx % D1;
    int kk = idx / D1;
    int hd = kk / D1;
    int k = kk - hd * D1;
    g_W2p[idx] = 0.1f * W2[(size_t)k * D2 + hd * D1 + f];
}

// ---------------- pooling (sorted batch -> segment boundaries) ----------------
__global__ void bnd_kernel(const int* __restrict__ batch) {
    int n = blockIdx.x * blockDim.x + threadIdx.x;
    if (n >= NN) return;
    int bn = geti(batch, n);
    if (bn < 0) bn = 0; if (bn > NB - 1) bn = NB - 1;
    int bp;
    if (n == 0) bp = -1;
    else {
        bp = geti(batch, n - 1);
        if (bp < 0) bp = 0; if (bp > NB - 1) bp = NB - 1;
    }
    for (int b = bp + 1; b <= bn; b++) g_bnd[b] = n;
    if (n == NN - 1) for (int b = bn + 1; b <= NB; b++) g_bnd[b] = NN;
}

__global__ __launch_bounds__(256) void pool2_kernel() {
    int b = blockIdx.x;
    int s = g_bnd[b], e = g_bnd[b + 1];
    float mx[4] = {0.f, 0.f, 0.f, 0.f};
    float sm[4] = {0.f, 0.f, 0.f, 0.f};
    for (int n = s; n < e; n++) {
        const float* hr = &g_h2[(size_t)n * D1];
#pragma unroll
        for (int u = 0; u < 4; u++) {
            int c = threadIdx.x + u * 256;
            if (c < D1) {
                float v = hr[c];
                sm[u] += v;
                mx[u] = fmaxf(mx[u], v);
            }
        }
    }
    float inv = 1.f / fmaxf((float)(e - s), 1.f);
#pragma unroll
    for (int u = 0; u < 4; u++) {
        int c = threadIdx.x + u * 256;
        if (c < D1) {
            g_gcat[b * 1560 + c] = mx[u];
            g_gcat[b * 1560 + D1 + c] = sm[u] * inv;
        }
    }
}

// ---------------- protein branch ----------------
__global__ void paccum_kernel(const int* __restrict__ target, const float* __restrict__ Wc) {
    int b = blockIdx.x;
    int tid = threadIdx.x;
    __shared__ int tg[1000];
    for (int i = tid; i < 1000; i += 256) {
        int v = geti(target, (long long)b * 1000 + i);
        tg[i] = (v >= 0 && v < 26) ? v : 0;
    }
    __syncthreads();
    float acc[26];
#pragma unroll
    for (int v = 0; v < 26; v++) acc[v] = 0.f;
    int o = tid >> 3, k = tid & 7;
    for (int i = 0; i < 1000; i++) acc[tg[i]] += Wc[o * 8000 + i * 8 + k];
#pragma unroll
    for (int v = 0; v < 26; v++) g_pacc[(b * 26 + v) * 256 + tid] = acc[v];
}

__global__ void conv_kernel(const float* __restrict__ emb, const float* __restrict__ bc) {
    int o = blockIdx.x, b = blockIdx.y;
    __shared__ float sA[26 * 8];
    for (int i = threadIdx.x; i < 208; i += 128)
        sA[i] = g_pacc[(b * 26 + (i >> 3)) * 256 + o * 8 + (i & 7)];
    __syncthreads();
    int t = threadIdx.x;
    if (t < 121) {
        float s = 0.f;
#pragma unroll
        for (int v = 0; v < 26; v++)
#pragma unroll
            for (int k = 0; k < 8; k++) s += sA[v * 8 + k] * emb[v * 128 + t + k];
        g_c[b * 3872 + o * 121 + t] = s + bc[o];
    }
}

// ---------------- launcher ----------------
static int find_sz(const int* in_sizes, int n_in, long long want,
                   unsigned char* used, int fallback) {
    for (int i = 0; i < n_in; i++)
        if (!used[i] && (long long)in_sizes[i] == want) { used[i] = 1; return i; }
    if (fallback >= 0 && fallback < n_in) return fallback;
    return 0;
}

template <typename T>
static T* sym_addr(const void* symbol) {
    void* p = nullptr;
    cudaGetSymbolAddress(&p, symbol);
    return (T*)p;
}

extern "C" void kernel_launch(void* const* d_in, const int* in_sizes, int n_in,
                              void* d_out, int out_size) {
    long long S = 0;
    for (int i = 0; i < n_in; i++) if (in_sizes[i] == 780000)  { S = 1; break; }
    if (!S) { for (int i = 0; i < n_in; i++) if (in_sizes[i] == 3120000) { S = 4; break; } }
    if (!S) S = 1;

    float* p_h1pre = sym_addr<float>(g_h1pre);
    float* p_h2    = sym_addr<float>(g_h2);
    float* p_hagg  = sym_addr<float>(g_hagg);
    float* p_W2p   = sym_addr<float>(g_W2p);
    float* p_gcat  = sym_addr<float>(g_gcat);
    float* p_g1    = sym_addr<float>(g_g1);
    float* p_cat   = sym_addr<float>(g_cat);
    float* p_c     = sym_addr<float>(g_c);
    float* p_f1    = sym_addr<float>(g_f1);
    float* p_f2    = sym_addr<float>(g_f2);

    GroupPtrs gp;
    const float* g128p[2] = {nullptr, nullptr};
    int n780 = 0, n7800 = 0, n512 = 0, n128 = 0;
    for (int i = 0; i < 4; i++) gp.p780[i] = nullptr;
    gp.p7800[0] = gp.p7800[1] = nullptr;
    gp.p512[0] = gp.p512[1] = nullptr;
    for (int i = 0; i < n_in; i++) {
        long long sz = in_sizes[i];
        if (sz == 780 * S  && n780  < 4) gp.p780[n780++]   = (const float*)d_in[i];
        else if (sz == 7800 * S && n7800 < 2) gp.p7800[n7800++] = (const float*)d_in[i];
        else if (sz == 512 * S  && n512  < 2) gp.p512[n512++]   = (const float*)d_in[i];
        else if (sz == 128 * S  && n128  < 2) g128p[n128++]     = (const float*)d_in[i];
    }
    for (int i = 0; i < 4; i++) if (!gp.p780[i])  gp.p780[i]  = (const float*)d_in[0];
    for (int i = 0; i < 2; i++) if (!gp.p7800[i]) gp.p7800[i] = (const float*)d_in[0];
    for (int i = 0; i < 2; i++) if (!gp.p512[i])  gp.p512[i]  = (const float*)d_in[0];
    for (int i = 0; i < 2; i++) if (!g128p[i])    g128p[i]    = (const float*)d_in[0];

    unsigned char used[256];
    for (int i = 0; i < 256; i++) used[i] = 0;
    const float* x      = (const float*)d_in[find_sz(in_sizes, n_in, 780000 * S, used, 0)];
    const int*   ei     = (const int*)  d_in[find_sz(in_sizes, n_in, 80000 * S,  used, 1)];
    const int*   batch  = (const int*)  d_in[find_sz(in_sizes, n_in, 10000 * S,  used, 2)];
    const int*   target = (const int*)  d_in[find_sz(in_sizes, n_in, 64000 * S,  used, 3)];
    const float* W1     = (const float*)d_in[find_sz(in_sizes, n_in, 60840 * S,  used, 4)];
    const float* W2     = (const float*)d_in[find_sz(in_sizes, n_in, 6084000 * S, used, 8)];
    const float* Wg1    = (const float*)d_in[find_sz(in_sizes, n_in, 2340000 * S, used, 12)];
    const float* bg1    = (const float*)d_in[find_sz(in_sizes, n_in, 1500 * S,   used, 13)];
    const float* Wg2    = (const float*)d_in[find_sz(in_sizes, n_in, 192000 * S, used, 14)];
    const float* emb    = (const float*)d_in[find_sz(in_sizes, n_in, 3328 * S,   used, 16)];
    const float* Wc     = (const float*)d_in[find_sz(in_sizes, n_in, 256000 * S, used, 17)];
    const float* bc     = (const float*)d_in[find_sz(in_sizes, n_in, 32 * S,     used, 18)];
    const float* Wxt    = (const float*)d_in[find_sz(in_sizes, n_in, 495616 * S, used, 19)];
    const float* Wf1    = (const float*)d_in[find_sz(in_sizes, n_in, 262144 * S, used, 21)];
    const float* bf1    = (const float*)d_in[find_sz(in_sizes, n_in, 1024 * S,   used, 22)];
    const float* Wf2    = (const float*)d_in[find_sz(in_sizes, n_in, 524288 * S, used, 23)];
    const float* bo     = (const float*)d_in[find_sz(in_sizes, n_in, 1 * S,      used, 26)];
    const float* bg2 = g128p[0];
    const float* bxt = g128p[1];
    float* out = (float*)d_out;

    detect_i64_kernel<<<1, 1>>>(ei);
    norms_kernel<<<8, 256>>>(gp);
    resolve_kernel<<<1, 1>>>(gp);

    prep_zero_kernel<<<(NN + 255) / 256, 256>>>();
    count_kernel<<<(NT + 255) / 256, 256>>>(ei);
    scan_kernel<<<1, 1024>>>();
    scatter_kernel<<<(NT + 255) / 256, 256>>>(ei);

    // GAT1
    sgemm128<<<dim3(7, 79), 256>>>(x, W1, nullptr, p_h1pre, NN, 78, D1, 0, -1);
    scores1_kernel<<<NN, 128>>>();
    alpha_kernel<<<(NN * NH + 255) / 256, 256>>>();
    agg1_kernel<<<NN, 256>>>();

    // GAT2
    ws2_kernel<<<(D1 * NH + 255) / 256, 256>>>(W2);
    scores2_kernel<<<NN, 128>>>();
    alpha_kernel<<<(NN * NH + 255) / 256, 256>>>();
    agg2_kernel<<<NN, 256>>>();
    packw2_kernel<<<(D2 * D1 + 255) / 256, 256>>>(W2);
    sgemm128<<<dim3(7, 79), 256>>>(p_hagg, p_W2p, nullptr, p_h2, NN, D2, D1, 1, SL_B2);

    // pooling + graph MLP
    bnd_kernel<<<(NN + 255) / 256, 256>>>(batch);
    pool2_kernel<<<NB, 256>>>();
    gemm8<<<dim3(12, 8), 128>>>(p_gcat, Wg1, bg1, p_g1, NB, 1560, 1500, 1, 1500, 0, -1, -1);
    gemm8<<<dim3(1, 8), 128>>>(p_g1, Wg2, bg2, p_cat, NB, 1500, 128, 1, 256, 0, -1, -1);

    // protein branch
    paccum_kernel<<<NB, 256>>>(target, Wc);
    conv_kernel<<<dim3(32, NB), 128>>>(emb, bc);
    gemm8<<<dim3(1, 8), 128>>>(p_c, Wxt, bxt, p_cat, NB, 3872, 128, 0, 256, 128, -1, -1);

    // head MLP
    gemm8<<<dim3(8, 8), 128>>>(p_cat, Wf1, bf1, p_f1, NB, 256, 1024, 1, 1024, 0, -1, -1);
    gemm8<<<dim3(4, 8), 128>>>(p_f1, Wf2, nullptr, p_f2, NB, 1024, 512, 1, 512, 0, -1, SL_BF2);
    gemm8<<<dim3(1, 8), 128>>>(p_f2, nullptr, bo, out, NB, 512, 1, 0, 1, 0, SL_WO, -1);
}

// round 14
// speedup vs baseline: 2.3033x; 1.7724x over previous
#include <cuda_runtime.h>
#include <math.h>

#define NN 10000
#define NE 40000
#define NT 50000
#define NB 64
#define NH 10
#define D1 780
#define D2 7800

#define SL_A1S 0
#define SL_A1D 1
#define SL_B1  2
#define SL_B2  3
#define SL_A2S 4
#define SL_A2D 5
#define SL_BF2 6
#define SL_WO  7

struct GroupPtrs {
    const float* p780[4];
    const float* p7800[2];
    const float* p512[2];
};

// ---------------- scratch ----------------
__device__ unsigned long long g_ptr[8];
__device__ float g_normbuf[8];
__device__ int   g_i64;
__device__ float g_h1pre[NN * D1];
__device__ float g_h[NN * D1];
__device__ float g_h2[NN * D1];
__device__ float g_es[NN * NH];
__device__ float g_ed[NN * NH];
__device__ float g_alpha[NT * NH];
__device__ int   g_deg[NN];
__device__ int   g_off[NN + 1];
__device__ int   g_cur[NN];
__device__ int   g_csrc[NT];
__device__ float g_hagg[(size_t)NN * D2];
__device__ float g_W2p[D2 * D1];
__device__ float g_ws2[D1 * NH];
__device__ float g_wd2[D1 * NH];
__device__ int   g_bnd[NB + 1];
__device__ float g_gcat[NB * 1560];
__device__ float g_g1[NB * 1500];
__device__ float g_cat[NB * 256];
__device__ float g_pacc[NB * 26 * 256];
__device__ float g_c[NB * 3872];
__device__ float g_f1[NB * 1024];
__device__ float g_f2[NB * 512];

__device__ __forceinline__ int geti(const int* p, long long i) {
    return g_i64 ? p[2 * i] : p[(size_t)i];
}

__global__ void detect_i64_kernel(const int* __restrict__ ei) {
    int odd_nonzero = 0;
    for (int k = 0; k < 64; k++) if (ei[2 * k + 1] != 0) odd_nonzero++;
    g_i64 = (odd_nonzero == 0) ? 1 : 0;
}

__global__ void norms_kernel(GroupPtrs gp) {
    __shared__ float sred[256];
    int b = blockIdx.x;
    const float* p = nullptr; int n = 0;
    if (b < 4)      { p = gp.p780[b];      n = 780; }
    else if (b < 6) { p = gp.p7800[b - 4]; n = 7800; }
    else            { p = gp.p512[b - 6];  n = 512; }
    float s = 0.f;
    if (p) for (int i = threadIdx.x; i < n; i += 256) s += fabsf(p[i]);
    sred[threadIdx.x] = s;
    __syncthreads();
    for (int d = 128; d > 0; d >>= 1) {
        if (threadIdx.x < d) sred[threadIdx.x] += sred[threadIdx.x + d];
        __syncthreads();
    }
    if (threadIdx.x == 0) g_normbuf[b] = sred[0];
}

__global__ void resolve_kernel(GroupPtrs gp) {
    const float EPS = 1e-12f;
    bool z0 = g_normbuf[6] < EPS, z1 = g_normbuf[7] < EPS;
    if (!z0 && z1) {
        g_ptr[SL_WO]  = (unsigned long long)gp.p512[0];
        g_ptr[SL_BF2] = (unsigned long long)gp.p512[1];
    } else {
        g_ptr[SL_BF2] = (unsigned long long)gp.p512[0];
        g_ptr[SL_WO]  = (unsigned long long)gp.p512[1];
    }
    int za[4], zb[4]; int na = 0, nb = 0;
    for (int i = 0; i < 4; i++) {
        if (g_normbuf[i] < EPS) zb[nb++] = i; else za[na++] = i;
    }
    int ia0 = 0, ia1 = 1, ib0 = 2, ib1 = 3;
    if (na == 2 && nb == 2) { ia0 = za[0]; ia1 = za[1]; ib0 = zb[0]; ib1 = zb[1]; }
    g_ptr[SL_A1S] = (unsigned long long)gp.p780[ia0];
    g_ptr[SL_A1D] = (unsigned long long)gp.p780[ia1];
    g_ptr[SL_B1]  = (unsigned long long)gp.p780[ib0];
    g_ptr[SL_B2]  = (unsigned long long)gp.p780[ib1];
    g_ptr[SL_A2S] = (unsigned long long)gp.p7800[0];
    g_ptr[SL_A2D] = (unsigned long long)gp.p7800[1];
}

// ---------------- prep + CSR ----------------
__global__ void prep_zero_kernel() {
    int i = blockIdx.x * blockDim.x + threadIdx.x;
    if (i < NN) g_deg[i] = 0;
}

__global__ void count_kernel(const int* __restrict__ ei) {
    int e = blockIdx.x * blockDim.x + threadIdx.x;
    if (e >= NT) return;
    int dst = (e < NE) ? geti(ei, NE + e) : (e - NE);
    if (dst >= 0 && dst < NN) atomicAdd(&g_deg[dst], 1);
}

__global__ void scan_kernel() {
    __shared__ int s[1024];
    int tid = threadIdx.x;
    const int CH = (NN + 1023) / 1024;
    int base = tid * CH;
    int sum = 0;
    for (int i = 0; i < CH; i++) { int idx = base + i; if (idx < NN) sum += g_deg[idx]; }
    s[tid] = sum;
    __syncthreads();
    for (int d = 1; d < 1024; d <<= 1) {
        int v = 0;
        if (tid >= d) v = s[tid - d];
        __syncthreads();
        s[tid] += v;
        __syncthreads();
    }
    int run = (tid == 0) ? 0 : s[tid - 1];
    for (int i = 0; i < CH; i++) {
        int idx = base + i;
        if (idx < NN) { g_off[idx] = run; g_cur[idx] = run; run += g_deg[idx]; }
    }
    if (tid == 1023) g_off[NN] = s[1023];
}

__global__ void scatter_kernel(const int* __restrict__ ei) {
    int e = blockIdx.x * blockDim.x + threadIdx.x;
    if (e >= NT) return;
    int src = (e < NE) ? geti(ei, e) : (e - NE);
    int dst = (e < NE) ? geti(ei, NE + e) : (e - NE);
    if (dst < 0 || dst >= NN || src < 0 || src >= NN) return;
    int pos = atomicAdd(&g_cur[dst], 1);
    if (pos >= 0 && pos < NT) g_csrc[pos] = src;
}

// ---------------- tf32 tensor-core GEMM ----------------
// C[M,N] = act( A[M,K] @ B[K,N] + bias )   (A,B row-major fp32, tf32 compute)
// 128x128 block tile, BK=16, 256 threads = 8 warps (2 m x 4 n), warp tile 64x32.
__global__ __launch_bounds__(256) void tf32_gemm(
    const float* __restrict__ A, const float* __restrict__ B,
    float* __restrict__ C, int M, int K, int N, int act, int bias_slot)
{
    __shared__ unsigned int As[16][136];
    __shared__ unsigned int Bs[16][136];
    const float* bias = (bias_slot >= 0) ? (const float*)g_ptr[bias_slot] : nullptr;
    int tid = threadIdx.x;
    int lane = tid & 31, wid = tid >> 5;
    int g = lane >> 2, t = lane & 3;
    int mBase = (wid & 1) * 64;
    int nBase = (wid >> 1) * 32;
    int rowBase = blockIdx.y * 128, colBase = blockIdx.x * 128;

    float acc[4][4][4];
#pragma unroll
    for (int mt = 0; mt < 4; mt++)
#pragma unroll
        for (int nt = 0; nt < 4; nt++)
#pragma unroll
            for (int q = 0; q < 4; q++) acc[mt][nt][q] = 0.f;

    for (int k0 = 0; k0 < K; k0 += 16) {
        // A tile: 16(k) x 128(m), stored As[k][m]
#pragma unroll
        for (int i = 0; i < 8; i++) {
            int idx = i * 256 + tid;
            int m = idx >> 4, k = idx & 15;
            int gr = rowBase + m, gk = k0 + k;
            float v = (gr < M && gk < K) ? A[(size_t)gr * K + gk] : 0.f;
            unsigned int tv;
            asm("cvt.rna.tf32.f32 %0, %1;" : "=r"(tv) : "f"(v));
            As[k][m] = tv;
        }
        // B tile: 16(k) x 128(n), stored Bs[k][n]
#pragma unroll
        for (int i = 0; i < 8; i++) {
            int idx = i * 256 + tid;
            int k = idx >> 7, n = idx & 127;
            int gk = k0 + k, gc = colBase + n;
            float v = (gk < K && gc < N) ? B[(size_t)gk * N + gc] : 0.f;
            unsigned int tv;
            asm("cvt.rna.tf32.f32 %0, %1;" : "=r"(tv) : "f"(v));
            Bs[k][n] = tv;
        }
        __syncthreads();
#pragma unroll
        for (int kk = 0; kk < 16; kk += 8) {
            unsigned int af[4][4], bf[4][2];
#pragma unroll
            for (int mt = 0; mt < 4; mt++) {
                int mr = mBase + mt * 16 + g;
                af[mt][0] = As[kk + t][mr];
                af[mt][1] = As[kk + t][mr + 8];
                af[mt][2] = As[kk + t + 4][mr];
                af[mt][3] = As[kk + t + 4][mr + 8];
            }
#pragma unroll
            for (int nt = 0; nt < 4; nt++) {
                int nc = nBase + nt * 8 + g;
                bf[nt][0] = Bs[kk + t][nc];
                bf[nt][1] = Bs[kk + t + 4][nc];
            }
#pragma unroll
            for (int mt = 0; mt < 4; mt++)
#pragma unroll
                for (int nt = 0; nt < 4; nt++) {
                    asm volatile(
                        "mma.sync.aligned.m16n8k8.row.col.f32.tf32.tf32.f32 "
                        "{%0,%1,%2,%3}, {%4,%5,%6,%7}, {%8,%9}, {%0,%1,%2,%3};"
                        : "+f"(acc[mt][nt][0]), "+f"(acc[mt][nt][1]),
                          "+f"(acc[mt][nt][2]), "+f"(acc[mt][nt][3])
                        : "r"(af[mt][0]), "r"(af[mt][1]),
                          "r"(af[mt][2]), "r"(af[mt][3]),
                          "r"(bf[nt][0]), "r"(bf[nt][1]));
                }
        }
        __syncthreads();
    }
    // epilogue: c0:(g, 2t) c1:(g, 2t+1) c2:(g+8, 2t) c3:(g+8, 2t+1)
#pragma unroll
    for (int mt = 0; mt < 4; mt++) {
        int r0 = rowBase + mBase + mt * 16 + g;
        int r1 = r0 + 8;
#pragma unroll
        for (int nt = 0; nt < 4; nt++) {
            int c0 = colBase + nBase + nt * 8 + 2 * t;
            int c1 = c0 + 1;
            float bv0 = (bias && c0 < N) ? bias[c0] : 0.f;
            float bv1 = (bias && c1 < N) ? bias[c1] : 0.f;
            float v;
            if (r0 < M && c0 < N) {
                v = acc[mt][nt][0] + bv0;
                if (act == 1) v = fmaxf(v, 0.f);
                C[(size_t)r0 * N + c0] = v;
            }
            if (r0 < M && c1 < N) {
                v = acc[mt][nt][1] + bv1;
                if (act == 1) v = fmaxf(v, 0.f);
                C[(size_t)r0 * N + c1] = v;
            }
            if (r1 < M && c0 < N) {
                v = acc[mt][nt][2] + bv0;
                if (act == 1) v = fmaxf(v, 0.f);
                C[(size_t)r1 * N + c0] = v;
            }
            if (r1 < M && c1 < N) {
                v = acc[mt][nt][3] + bv1;
                if (act == 1) v = fmaxf(v, 0.f);
                C[(size_t)r1 * N + c1] = v;
            }
        }
    }
}

// ---------------- tiled fp32 SGEMM (GAT1 pre-projection, small K) ------------
__global__ __launch_bounds__(256) void sgemm128(
    const float* __restrict__ A, const float* __restrict__ B,
    const float* bias, float* __restrict__ C,
    int M, int K, int N, int act, int bias_slot)
{
    __shared__ float As[8][128];
    __shared__ float Bs[8][128];
    if (bias_slot >= 0) bias = (const float*)g_ptr[bias_slot];
    int tid = threadIdx.x;
    int tx = tid & 15, ty = tid >> 4;
    int rowBase = blockIdx.y * 128, colBase = blockIdx.x * 128;
    unsigned long long acc2[8][4];
#pragma unroll
    for (int i = 0; i < 8; i++)
#pragma unroll
        for (int j = 0; j < 4; j++) acc2[i][j] = 0ULL;

    for (int k0 = 0; k0 < K; k0 += 8) {
#pragma unroll
        for (int i = 0; i < 4; i++) {
            int l = i * 256 + tid;
            int r = l >> 3, k = l & 7;
            int gr = rowBase + r, gk = k0 + k;
            As[k][r] = (gr < M && gk < K) ? A[(size_t)gr * K + gk] : 0.f;
        }
#pragma unroll
        for (int i = 0; i < 4; i++) {
            int l = i * 256 + tid;
            int k = l >> 7, c = l & 127;
            int gk = k0 + k, gc = colBase + c;
            Bs[k][c] = (gk < K && gc < N) ? B[(size_t)gk * N + gc] : 0.f;
        }
        __syncthreads();
#pragma unroll
        for (int k = 0; k < 8; k++) {
            float4 a0 = *reinterpret_cast<const float4*>(&As[k][ty * 8]);
            float4 a1 = *reinterpret_cast<const float4*>(&As[k][ty * 8 + 4]);
            float a[8] = {a0.x, a0.y, a0.z, a0.w, a1.x, a1.y, a1.z, a1.w};
            const unsigned long long* bp =
                reinterpret_cast<const unsigned long long*>(&Bs[k][tx * 8]);
            unsigned long long b2[4] = {bp[0], bp[1], bp[2], bp[3]};
#pragma unroll
            for (int i = 0; i < 8; i++) {
                unsigned long long a2;
                asm("mov.b64 %0, {%1, %1};" : "=l"(a2) : "f"(a[i]));
#pragma unroll
                for (int j = 0; j < 4; j++)
                    asm("fma.rn.f32x2 %0, %1, %2, %0;"
                        : "+l"(acc2[i][j]) : "l"(a2), "l"(b2[j]));
            }
        }
        __syncthreads();
    }
#pragma unroll
    for (int i = 0; i < 8; i++) {
        int r = rowBase + ty * 8 + i;
        if (r < M) {
#pragma unroll
            for (int j = 0; j < 4; j++) {
                float lo, hi;
                asm("mov.b64 {%0, %1}, %2;" : "=f"(lo), "=f"(hi) : "l"(acc2[i][j]));
                int c0 = colBase + tx * 8 + 2 * j;
                if (c0 < N) {
                    float v = lo + (bias ? bias[c0] : 0.f);
                    if (act == 1) v = fmaxf(v, 0.f);
                    C[(size_t)r * N + c0] = v;
                }
                if (c0 + 1 < N) {
                    float v = hi + (bias ? bias[c0 + 1] : 0.f);
                    if (act == 1) v = fmaxf(v, 0.f);
                    C[(size_t)r * N + c0 + 1] = v;
                }
            }
        }
    }
}

// ---------------- small GEMM (tail layers) ----------------
__global__ __launch_bounds__(128) void gemm8(
    const float* __restrict__ A, const float* B, const float* bias,
    float* __restrict__ C, int M, int K, int N, int act,
    int ldc, int coff, int b_slot, int bias_slot)
{
    __shared__ float sA[8][512];
    if (b_slot >= 0) B = (const float*)g_ptr[b_slot];
    if (bias_slot >= 0) bias = (const float*)g_ptr[bias_slot];
    int n = blockIdx.x * 128 + threadIdx.x;
    int m0 = blockIdx.y * 8;
    float acc[8];
#pragma unroll
    for (int r = 0; r < 8; r++) acc[r] = 0.f;
    for (int k0 = 0; k0 < K; k0 += 512) {
        int kc = min(512, K - k0);
        for (int l = threadIdx.x; l < 8 * kc; l += 128) {
            int r = l / kc, k = l - r * kc;
            int gr = m0 + r;
            sA[r][k] = (gr < M) ? A[(size_t)gr * K + k0 + k] : 0.f;
        }
        __syncthreads();
        if (n < N) {
            for (int k = 0; k < kc; k++) {
                float b = B[(size_t)(k0 + k) * N + n];
#pragma unroll
                for (int r = 0; r < 8; r++) acc[r] += sA[r][k] * b;
            }
        }
        __syncthreads();
    }
    if (n < N) {
        float bv = bias ? bias[n] : 0.f;
#pragma unroll
        for (int r = 0; r < 8; r++) {
            int gr = m0 + r;
            if (gr < M) {
                float v = acc[r] + bv;
                if (act == 1) v = fmaxf(v, 0.f);
                C[(size_t)gr * ldc + coff + n] = v;
            }
        }
    }
}

// ---------------- attention scores ----------------
__global__ void scores1_kernel() {
    const float* a1s = (const float*)g_ptr[SL_A1S];
    const float* a1d = (const float*)g_ptr[SL_A1D];
    int i = blockIdx.x;
    __shared__ float row[D1];
    for (int c = threadIdx.x; c < D1; c += blockDim.x) row[c] = g_h1pre[(size_t)i * D1 + c];
    __syncthreads();
    int t = threadIdx.x;
    if (t < 2 * NH) {
        int hd = t % NH;
        const float* a = (t < NH) ? a1s : a1d;
        float s = 0.f;
        for (int f = 0; f < 78; f++) s += row[hd * 78 + f] * a[hd * 78 + f];
        if (t < NH) g_es[i * NH + hd] = s; else g_ed[i * NH + hd] = s;
    }
}

// one block per k-row of W2: load the 7800-wide row once (coalesced), then
// 8 warps shfl-reduce the 20 dot products.
__global__ __launch_bounds__(256) void ws2_kernel(const float* __restrict__ W2) {
    __shared__ float wrow[D2];
    const float* a2s = (const float*)g_ptr[SL_A2S];
    const float* a2d = (const float*)g_ptr[SL_A2D];
    int k = blockIdx.x;
    for (int i = threadIdx.x; i < D2; i += 256) wrow[i] = W2[(size_t)k * D2 + i];
    __syncthreads();
    int wid = threadIdx.x >> 5, lane = threadIdx.x & 31;
    for (int o = wid; o < 2 * NH; o += 8) {
        int hd = o >> 1, sel = o & 1;
        const float* av = sel ? &a2d[hd * D1] : &a2s[hd * D1];
        const float* wr = &wrow[hd * D1];
        float s = 0.f;
        for (int f = lane; f < D1; f += 32) s += wr[f] * av[f];
#pragma unroll
        for (int d = 16; d > 0; d >>= 1) s += __shfl_xor_sync(0xffffffff, s, d);
        if (lane == 0) {
            if (sel) g_wd2[k * NH + hd] = s; else g_ws2[k * NH + hd] = s;
        }
    }
}

__global__ void scores2_kernel() {
    int i = blockIdx.x;
    __shared__ float row[D1];
    for (int c = threadIdx.x; c < D1; c += blockDim.x) row[c] = g_h[(size_t)i * D1 + c];
    __syncthreads();
    int t = threadIdx.x;
    if (t < 2 * NH) {
        int hd = t % NH;
        const float* w = (t < NH) ? g_ws2 : g_wd2;
        float s = 0.f;
        for (int k = 0; k < D1; k++) s += row[k] * w[k * NH + hd];
        if (t < NH) g_es[i * NH + hd] = s; else g_ed[i * NH + hd] = s;
    }
}

__global__ void alpha_kernel() {
    int idx = blockIdx.x * blockDim.x + threadIdx.x;
    if (idx >= NN * NH) return;
    int d = idx / NH, hd = idx - d * NH;
    int s = g_off[d], e = g_off[d + 1];
    if (e <= s) return;
    float edv = g_ed[idx];
    float m = -1e30f;
    for (int j = s; j < e; j++) {
        float z = g_es[g_csrc[j] * NH + hd] + edv;
        z = (z > 0.f) ? z : 0.2f * z;
        m = fmaxf(m, z);
    }
    float sum = 0.f;
    for (int j = s; j < e; j++) {
        float z = g_es[g_csrc[j] * NH + hd] + edv;
        z = (z > 0.f) ? z : 0.2f * z;
        float ex = expf(z - m);
        g_alpha[j * NH + hd] = ex;
        sum += ex;
    }
    float inv = 1.f / sum;
    for (int j = s; j < e; j++) g_alpha[j * NH + hd] *= inv;
}

__global__ __launch_bounds__(256) void agg1_kernel() {
    const float* b1 = (const float*)g_ptr[SL_B1];
    int d = blockIdx.x;
    int s = g_off[d], e = g_off[d + 1];
    __shared__ int ssrc[64];
    __shared__ float sal[64 * NH];
    float acc[4] = {0.f, 0.f, 0.f, 0.f};
    int hd[4];
#pragma unroll
    for (int u = 0; u < 4; u++) {
        int c = threadIdx.x + u * 256;
        hd[u] = (c < D1) ? (c / 78) : 0;
    }
    for (int j0 = s; j0 < e; j0 += 64) {
        int cnt = min(64, e - j0);
        for (int q = threadIdx.x; q < cnt; q += 256) ssrc[q] = g_csrc[j0 + q];
        for (int q = threadIdx.x; q < cnt * NH; q += 256) sal[q] = g_alpha[j0 * NH + q];
        __syncthreads();
        for (int jj = 0; jj < cnt; jj++) {
            const float* hr = &g_h1pre[(size_t)ssrc[jj] * D1];
#pragma unroll
            for (int u = 0; u < 4; u++) {
                int c = threadIdx.x + u * 256;
                if (c < D1) acc[u] += sal[jj * NH + hd[u]] * hr[c];
            }
        }
        __syncthreads();
    }
#pragma unroll
    for (int u = 0; u < 4; u++) {
        int c = threadIdx.x + u * 256;
        if (c < D1) {
            float z = acc[u] + b1[c];
            g_h[(size_t)d * D1 + c] = (z > 0.f) ? z : (expf(z) - 1.f);
        }
    }
}

__global__ __launch_bounds__(256) void agg2_kernel() {
    int d = blockIdx.x;
    int s = g_off[d], e = g_off[d + 1];
    __shared__ int ssrc[32];
    __shared__ float sal[32 * NH];
    float acc[4][NH];
#pragma unroll
    for (int u = 0; u < 4; u++)
#pragma unroll
        for (int t = 0; t < NH; t++) acc[u][t] = 0.f;
    for (int j0 = s; j0 < e; j0 += 32) {
        int cnt = min(32, e - j0);
        for (int q = threadIdx.x; q < cnt; q += 256) ssrc[q] = g_csrc[j0 + q];
        for (int q = threadIdx.x; q < cnt * NH; q += 256) sal[q] = g_alpha[j0 * NH + q];
        __syncthreads();
        for (int jj = 0; jj < cnt; jj++) {
            const float* hr = &g_h[(size_t)ssrc[jj] * D1];
#pragma unroll
            for (int u = 0; u < 4; u++) {
                int c = threadIdx.x + u * 256;
                if (c < D1) {
                    float v = hr[c];
#pragma unroll
                    for (int t = 0; t < NH; t++) acc[u][t] += sal[jj * NH + t] * v;
                }
            }
        }
        __syncthreads();
    }
#pragma unroll
    for (int u = 0; u < 4; u++) {
        int c = threadIdx.x + u * 256;
        if (c < D1) {
#pragma unroll
            for (int t = 0; t < NH; t++)
                g_hagg[(size_t)d * D2 + t * D1 + c] = acc[u][t];
        }
    }
}

__global__ void packw2_kernel(const float* __restrict__ W2) {
    int idx = blockIdx.x * blockDim.x + threadIdx.x;
    if (idx >= D2 * D1) return;
    int f = idx % D1;
    int kk = idx / D1;
    int hd = kk / D1;
    int k = kk - hd * D1;
    g_W2p[idx] = 0.1f * W2[(size_t)k * D2 + hd * D1 + f];
}

// ---------------- pooling ----------------
__global__ void bnd_kernel(const int* __restrict__ batch) {
    int n = blockIdx.x * blockDim.x + threadIdx.x;
    if (n >= NN) return;
    int bn = geti(batch, n);
    if (bn < 0) bn = 0; if (bn > NB - 1) bn = NB - 1;
    int bp;
    if (n == 0) bp = -1;
    else {
        bp = geti(batch, n - 1);
        if (bp < 0) bp = 0; if (bp > NB - 1) bp = NB - 1;
    }
    for (int b = bp + 1; b <= bn; b++) g_bnd[b] = n;
    if (n == NN - 1) for (int b = bn + 1; b <= NB; b++) g_bnd[b] = NN;
}

__global__ __launch_bounds__(256) void pool2_kernel() {
    int b = blockIdx.x;
    int s = g_bnd[b], e = g_bnd[b + 1];
    float mx[4] = {0.f, 0.f, 0.f, 0.f};
    float sm[4] = {0.f, 0.f, 0.f, 0.f};
    for (int n = s; n < e; n++) {
        const float* hr = &g_h2[(size_t)n * D1];
#pragma unroll
        for (int u = 0; u < 4; u++) {
            int c = threadIdx.x + u * 256;
            if (c < D1) {
                float v = hr[c];
                sm[u] += v;
                mx[u] = fmaxf(mx[u], v);
            }
        }
    }
    float inv = 1.f / fmaxf((float)(e - s), 1.f);
#pragma unroll
    for (int u = 0; u < 4; u++) {
        int c = threadIdx.x + u * 256;
        if (c < D1) {
            g_gcat[b * 1560 + c] = mx[u];
            g_gcat[b * 1560 + D1 + c] = sm[u] * inv;
        }
    }
}

// ---------------- protein branch ----------------
__global__ void paccum_kernel(const int* __restrict__ target, const float* __restrict__ Wc) {
    int b = blockIdx.x;
    int tid = threadIdx.x;
    __shared__ int tg[1000];
    for (int i = tid; i < 1000; i += 256) {
        int v = geti(target, (long long)b * 1000 + i);
        tg[i] = (v >= 0 && v < 26) ? v : 0;
    }
    __syncthreads();
    float acc[26];
#pragma unroll
    for (int v = 0; v < 26; v++) acc[v] = 0.f;
    int o = tid >> 3, k = tid & 7;
    for (int i = 0; i < 1000; i++) acc[tg[i]] += Wc[o * 8000 + i * 8 + k];
#pragma unroll
    for (int v = 0; v < 26; v++) g_pacc[(b * 26 + v) * 256 + tid] = acc[v];
}

__global__ void conv_kernel(const float* __restrict__ emb, const float* __restrict__ bc) {
    int o = blockIdx.x, b = blockIdx.y;
    __shared__ float sA[26 * 8];
    for (int i = threadIdx.x; i < 208; i += 128)
        sA[i] = g_pacc[(b * 26 + (i >> 3)) * 256 + o * 8 + (i & 7)];
    __syncthreads();
    int t = threadIdx.x;
    if (t < 121) {
        float s = 0.f;
#pragma unroll
        for (int v = 0; v < 26; v++)
#pragma unroll
            for (int k = 0; k < 8; k++) s += sA[v * 8 + k] * emb[v * 128 + t + k];
        g_c[b * 3872 + o * 121 + t] = s + bc[o];
    }
}

// ---------------- launcher ----------------
static int find_sz(const int* in_sizes, int n_in, long long want,
                   unsigned char* used, int fallback) {
    for (int i = 0; i < n_in; i++)
        if (!used[i] && (long long)in_sizes[i] == want) { used[i] = 1; return i; }
    if (fallback >= 0 && fallback < n_in) return fallback;
    return 0;
}

template <typename T>
static T* sym_addr(const void* symbol) {
    void* p = nullptr;
    cudaGetSymbolAddress(&p, symbol);
    return (T*)p;
}

extern "C" void kernel_launch(void* const* d_in, const int* in_sizes, int n_in,
                              void* d_out, int out_size) {
    long long S = 0;
    for (int i = 0; i < n_in; i++) if (in_sizes[i] == 780000)  { S = 1; break; }
    if (!S) { for (int i = 0; i < n_in; i++) if (in_sizes[i] == 3120000) { S = 4; break; } }
    if (!S) S = 1;

    float* p_h1pre = sym_addr<float>(g_h1pre);
    float* p_h2    = sym_addr<float>(g_h2);
    float* p_hagg  = sym_addr<float>(g_hagg);
    float* p_W2p   = sym_addr<float>(g_W2p);
    float* p_gcat  = sym_addr<float>(g_gcat);
    float* p_g1    = sym_addr<float>(g_g1);
    float* p_cat   = sym_addr<float>(g_cat);
    float* p_c     = sym_addr<float>(g_c);
    float* p_f1    = sym_addr<float>(g_f1);
    float* p_f2    = sym_addr<float>(g_f2);

    GroupPtrs gp;
    const float* g128p[2] = {nullptr, nullptr};
    int n780 = 0, n7800 = 0, n512 = 0, n128 = 0;
    for (int i = 0; i < 4; i++) gp.p780[i] = nullptr;
    gp.p7800[0] = gp.p7800[1] = nullptr;
    gp.p512[0] = gp.p512[1] = nullptr;
    for (int i = 0; i < n_in; i++) {
        long long sz = in_sizes[i];
        if (sz == 780 * S  && n780  < 4) gp.p780[n780++]   = (const float*)d_in[i];
        else if (sz == 7800 * S && n7800 < 2) gp.p7800[n7800++] = (const float*)d_in[i];
        else if (sz == 512 * S  && n512  < 2) gp.p512[n512++]   = (const float*)d_in[i];
        else if (sz == 128 * S  && n128  < 2) g128p[n128++]     = (const float*)d_in[i];
    }
    for (int i = 0; i < 4; i++) if (!gp.p780[i])  gp.p780[i]  = (const float*)d_in[0];
    for (int i = 0; i < 2; i++) if (!gp.p7800[i]) gp.p7800[i] = (const float*)d_in[0];
    for (int i = 0; i < 2; i++) if (!gp.p512[i])  gp.p512[i]  = (const float*)d_in[0];
    for (int i = 0; i < 2; i++) if (!g128p[i])    g128p[i]    = (const float*)d_in[0];

    unsigned char used[256];
    for (int i = 0; i < 256; i++) used[i] = 0;
    const float* x      = (const float*)d_in[find_sz(in_sizes, n_in, 780000 * S, used, 0)];
    const int*   ei     = (const int*)  d_in[find_sz(in_sizes, n_in, 80000 * S,  used, 1)];
    const int*   batch  = (const int*)  d_in[find_sz(in_sizes, n_in, 10000 * S,  used, 2)];
    const int*   target = (const int*)  d_in[find_sz(in_sizes, n_in, 64000 * S,  used, 3)];
    const float* W1     = (const float*)d_in[find_sz(in_sizes, n_in, 60840 * S,  used, 4)];
    const float* W2     = (const float*)d_in[find_sz(in_sizes, n_in, 6084000 * S, used, 8)];
    const float* Wg1    = (const float*)d_in[find_sz(in_sizes, n_in, 2340000 * S, used, 12)];
    const float* bg1    = (const float*)d_in[find_sz(in_sizes, n_in, 1500 * S,   used, 13)];
    const float* Wg2    = (const float*)d_in[find_sz(in_sizes, n_in, 192000 * S, used, 14)];
    const float* emb    = (const float*)d_in[find_sz(in_sizes, n_in, 3328 * S,   used, 16)];
    const float* Wc     = (const float*)d_in[find_sz(in_sizes, n_in, 256000 * S, used, 17)];
    const float* bc     = (const float*)d_in[find_sz(in_sizes, n_in, 32 * S,     used, 18)];
    const float* Wxt    = (const float*)d_in[find_sz(in_sizes, n_in, 495616 * S, used, 19)];
    const float* Wf1    = (const float*)d_in[find_sz(in_sizes, n_in, 262144 * S, used, 21)];
    const float* bf1    = (const float*)d_in[find_sz(in_sizes, n_in, 1024 * S,   used, 22)];
    const float* Wf2    = (const float*)d_in[find_sz(in_sizes, n_in, 524288 * S, used, 23)];
    const float* bo     = (const float*)d_in[find_sz(in_sizes, n_in, 1 * S,      used, 26)];
    const float* bg2 = g128p[0];
    const float* bxt = g128p[1];
    float* out = (float*)d_out;

    detect_i64_kernel<<<1, 1>>>(ei);
    norms_kernel<<<8, 256>>>(gp);
    resolve_kernel<<<1, 1>>>(gp);

    prep_zero_kernel<<<(NN + 255) / 256, 256>>>();
    count_kernel<<<(NT + 255) / 256, 256>>>(ei);
    scan_kernel<<<1, 1024>>>();
    scatter_kernel<<<(NT + 255) / 256, 256>>>(ei);

    // GAT1
    sgemm128<<<dim3(7, 79), 256>>>(x, W1, nullptr, p_h1pre, NN, 78, D1, 0, -1);
    scores1_kernel<<<NN, 128>>>();
    alpha_kernel<<<(NN * NH + 255) / 256, 256>>>();
    agg1_kernel<<<NN, 256>>>();

    // GAT2
    ws2_kernel<<<D1, 256>>>(W2);
    scores2_kernel<<<NN, 128>>>();
    alpha_kernel<<<(NN * NH + 255) / 256, 256>>>();
    agg2_kernel<<<NN, 256>>>();
    packw2_kernel<<<(D2 * D1 + 255) / 256, 256>>>(W2);
    tf32_gemm<<<dim3(7, 79), 256>>>(p_hagg, p_W2p, p_h2, NN, D2, D1, 1, SL_B2);

    // pooling + graph MLP
    bnd_kernel<<<(NN + 255) / 256, 256>>>(batch);
    pool2_kernel<<<NB, 256>>>();
    gemm8<<<dim3(12, 8), 128>>>(p_gcat, Wg1, bg1, p_g1, NB, 1560, 1500, 1, 1500, 0, -1, -1);
    gemm8<<<dim3(1, 8), 128>>>(p_g1, Wg2, bg2, p_cat, NB, 1500, 128, 1, 256, 0, -1, -1);

    // protein branch
    paccum_kernel<<<NB, 256>>>(target, Wc);
    conv_kernel<<<dim3(32, NB), 128>>>(emb, bc);
    gemm8<<<dim3(1, 8), 128>>>(p_c, Wxt, bxt, p_cat, NB, 3872, 128, 0, 256, 128, -1, -1);

    // head MLP
    gemm8<<<dim3(8, 8), 128>>>(p_cat, Wf1, bf1, p_f1, NB, 256, 1024, 1, 1024, 0, -1, -1);
    gemm8<<<dim3(4, 8), 128>>>(p_f1, Wf2, nullptr, p_f2, NB, 1024, 512, 1, 512, 0, -1, SL_BF2);
    gemm8<<<dim3(1, 8), 128>>>(p_f2, nullptr, bo, out, NB, 512, 1, 0, 1, 0, SL_WO, -1);
}